// round 2
// baseline (speedup 1.0000x reference)
#include <cuda_runtime.h>

#define N_NODES 100000
#define N_EDGES 1600000
#define IN_CH   500
#define F1      64      // H1*C1
#define H1      8
#define C1      8
#define H2      8
#define C2      3
#define F2      24      // H2*C2
#define NEG_SLOPE 0.2f

// ---------------- scratch (static device arrays; no allocation allowed) ----
__device__ float g_xw1 [N_NODES * F1];
__device__ float g_out1[N_NODES * F1];
__device__ float g_h1  [N_NODES * F1];
__device__ float g_al1s[N_NODES * H1];
__device__ float g_al1d[N_NODES * H1];
__device__ float g_s1  [N_NODES * H1];
__device__ float g_xw2 [N_NODES * F2];
__device__ float g_out2[N_NODES * F2];
__device__ float g_al2s[N_NODES * H2];
__device__ float g_al2d[N_NODES * H2];
__device__ float g_s2  [N_NODES * H2];
__device__ int   g_is64;

// ---------------- helpers --------------------------------------------------
__device__ __forceinline__ float leaky(float v) {
    return v > 0.f ? v : NEG_SLOPE * v;
}

// Fetch edge endpoint robustly w.r.t. int32 vs int64 storage.
__device__ __forceinline__ int edge_idx(const void* ei, int pos, int is64) {
    if (is64) return (int)((const long long*)ei)[pos];
    return ((const int*)ei)[pos];
}

// ---------------- K-1: detect edge_index dtype ------------------------------
// int64 little-endian with values < 2^31 => every odd 32-bit word is 0.
__global__ void detect_kernel(const unsigned int* __restrict__ ei) {
    if (threadIdx.x == 0 && blockIdx.x == 0) {
        int all0 = 1;
        for (int i = 0; i < 64; i++)
            if (ei[2 * i + 1] != 0u) { all0 = 0; break; }
        g_is64 = all0;
    }
}

// ---------------- K0: zero accumulators ------------------------------------
__global__ void zero_kernel() {
    int i = blockIdx.x * blockDim.x + threadIdx.x;
    float4 z = make_float4(0.f, 0.f, 0.f, 0.f);
    if (i < (N_NODES * F1) / 4) ((float4*)g_out1)[i] = z;
    if (i < (N_NODES * F2) / 4) ((float4*)g_out2)[i] = z;
    if (i < (N_NODES * H1) / 4) {
        ((float4*)g_s1)[i] = z;
        ((float4*)g_s2)[i] = z;
    }
}

// ---------------- K1: xw1 = x @ W1, fused per-head attention logits --------
// BM=64, BN=64, BK=16, 256 threads, 4x4 per-thread tile.
__global__ void gemm1_kernel(const float* __restrict__ x,
                             const float* __restrict__ W,
                             const float* __restrict__ a1s,
                             const float* __restrict__ a1d) {
    __shared__ float xs[16][64];   // [k][m]  (transposed so m is contiguous)
    __shared__ float ws[16][64];   // [k][n]
    const int tid = threadIdx.x;
    const int tx = tid & 15;       // col group (4 cols each)
    const int ty = tid >> 4;       // row group (4 rows each)
    const int m0 = blockIdx.x * 64;

    float acc[4][4];
#pragma unroll
    for (int i = 0; i < 4; i++)
#pragma unroll
        for (int j = 0; j < 4; j++) acc[i][j] = 0.f;

    for (int k0 = 0; k0 < IN_CH; k0 += 16) {
#pragma unroll
        for (int i = 0; i < 4; i++) {
            int idx = tid + i * 256;          // 0..1023
            int r  = idx >> 4, kk = idx & 15; // x tile element
            int row = m0 + r, k = k0 + kk;
            xs[kk][r] = (row < N_NODES && k < IN_CH)
                            ? x[(size_t)row * IN_CH + k] : 0.f;
            int kk2 = idx >> 6, n = idx & 63; // w tile element
            int k2 = k0 + kk2;
            ws[kk2][n] = (k2 < IN_CH) ? W[k2 * F1 + n] : 0.f;
        }
        __syncthreads();
#pragma unroll
        for (int kk = 0; kk < 16; kk++) {
            float4 av = *(const float4*)&xs[kk][ty * 4];
            float4 bv = *(const float4*)&ws[kk][tx * 4];
            float a[4] = {av.x, av.y, av.z, av.w};
            float b[4] = {bv.x, bv.y, bv.z, bv.w};
#pragma unroll
            for (int i = 0; i < 4; i++)
#pragma unroll
                for (int j = 0; j < 4; j++) acc[i][j] += a[i] * b[j];
        }
        __syncthreads();
    }

    // attention-logit weights for my 4 columns (flat [64] == h*8+c layout)
    float as0 = a1s[tx * 4 + 0], as1 = a1s[tx * 4 + 1],
          as2 = a1s[tx * 4 + 2], as3 = a1s[tx * 4 + 3];
    float ad0 = a1d[tx * 4 + 0], ad1 = a1d[tx * 4 + 1],
          ad2 = a1d[tx * 4 + 2], ad3 = a1d[tx * 4 + 3];

#pragma unroll
    for (int i = 0; i < 4; i++) {
        float ps = acc[i][0] * as0 + acc[i][1] * as1 +
                   acc[i][2] * as2 + acc[i][3] * as3;
        float pd = acc[i][0] * ad0 + acc[i][1] * ad1 +
                   acc[i][2] * ad2 + acc[i][3] * ad3;
        // threads tx and tx^1 cover the two halves of head h = tx/2
        ps += __shfl_xor_sync(0xffffffffu, ps, 1);
        pd += __shfl_xor_sync(0xffffffffu, pd, 1);
        int row = m0 + ty * 4 + i;
        if (row < N_NODES) {
            float4 v = make_float4(acc[i][0], acc[i][1], acc[i][2], acc[i][3]);
            *(float4*)&g_xw1[(size_t)row * F1 + tx * 4] = v;
            if ((tx & 1) == 0) {
                g_al1s[row * H1 + (tx >> 1)] = ps;
                g_al1d[row * H1 + (tx >> 1)] = pd;
            }
        }
    }
}

// ---------------- K2: layer-1 edge pass (8 lanes per edge) ------------------
__global__ void edge1_kernel(const void* __restrict__ ei) {
    int id = blockIdx.x * blockDim.x + threadIdx.x;   // exactly 8*N_EDGES
    int e = id >> 3;
    int l = id & 7;
    if (e >= N_EDGES) return;
    int is64 = g_is64;
    int src = edge_idx(ei, e, is64);
    int dst = edge_idx(ei, N_EDGES + e, is64);

    float al = g_al1s[src * H1 + l] + g_al1d[dst * H1 + l];
    float ex = __expf(leaky(al));
    atomicAdd(&g_s1[dst * H1 + l], ex);

    const float* xs = &g_xw1[(size_t)src * F1];
    float*       od = &g_out1[(size_t)dst * F1];
    int lane = threadIdx.x & 31;
    int gb = lane & 24;   // 8-lane group base within warp
#pragma unroll
    for (int c = 0; c < 8; c++) {
        float exc = __shfl_sync(0xffffffffu, ex, gb + c, 32); // ex of head c
        atomicAdd(&od[c * 8 + l], exc * xs[c * 8 + l]);
    }
}

// ---------------- K3: finalize layer 1 (self-loop + normalize + ELU) -------
__global__ void fin1_kernel(const float* __restrict__ b1) {
    int id = blockIdx.x * blockDim.x + threadIdx.x;   // N_NODES*H1 threads
    if (id >= N_NODES * H1) return;
    int n = id >> 3, h = id & 7;

    float al  = g_al1s[id] + g_al1d[id];
    float exs = __expf(leaky(al));                 // self-loop weight
    float s   = g_s1[id] + exs;
    float inv = 1.f / (s + 1e-16f);

    size_t base = (size_t)n * F1 + h * 8;
    float4 o0 = *(const float4*)&g_out1[base];
    float4 o1 = *(const float4*)&g_out1[base + 4];
    float4 x0 = *(const float4*)&g_xw1[base];
    float4 x1 = *(const float4*)&g_xw1[base + 4];
    float4 bb0 = *(const float4*)&b1[h * 8];
    float4 bb1 = *(const float4*)&b1[h * 8 + 4];

    float v[8];
    v[0] = (o0.x + exs * x0.x) * inv + bb0.x;
    v[1] = (o0.y + exs * x0.y) * inv + bb0.y;
    v[2] = (o0.z + exs * x0.z) * inv + bb0.z;
    v[3] = (o0.w + exs * x0.w) * inv + bb0.w;
    v[4] = (o1.x + exs * x1.x) * inv + bb1.x;
    v[5] = (o1.y + exs * x1.y) * inv + bb1.y;
    v[6] = (o1.z + exs * x1.z) * inv + bb1.z;
    v[7] = (o1.w + exs * x1.w) * inv + bb1.w;
#pragma unroll
    for (int i = 0; i < 8; i++)
        v[i] = v[i] > 0.f ? v[i] : expm1f(v[i]);   // ELU
    *(float4*)&g_h1[base]     = make_float4(v[0], v[1], v[2], v[3]);
    *(float4*)&g_h1[base + 4] = make_float4(v[4], v[5], v[6], v[7]);
}

// ---------------- K4: xw2 = h1 @ W2 + layer-2 logits (warp per node) -------
__global__ void gemm2_kernel(const float* __restrict__ W2,
                             const float* __restrict__ a2s,
                             const float* __restrict__ a2d) {
    __shared__ float w2s[64 * F2];
    __shared__ float hs[8][64];
    int tid = threadIdx.x, lane = tid & 31, w = tid >> 5;
    for (int i = tid; i < 64 * F2; i += 256) w2s[i] = W2[i];
    __syncthreads();

    int node = blockIdx.x * 8 + w;
    if (node >= N_NODES) return;

    hs[w][lane]      = g_h1[(size_t)node * F1 + lane];
    hs[w][lane + 32] = g_h1[(size_t)node * F1 + 32 + lane];
    __syncwarp();

    float acc = 0.f;
    if (lane < F2) {
#pragma unroll 8
        for (int k = 0; k < 64; k++) acc += hs[w][k] * w2s[k * F2 + lane];
        g_xw2[(size_t)node * F2 + lane] = acc;
    }
    float ps = (lane < F2) ? acc * a2s[lane] : 0.f;   // flat [24] = h*3+c
    float pd = (lane < F2) ? acc * a2d[lane] : 0.f;
    float ps1 = __shfl_down_sync(0xffffffffu, ps, 1);
    float ps2 = __shfl_down_sync(0xffffffffu, ps, 2);
    float pd1 = __shfl_down_sync(0xffffffffu, pd, 1);
    float pd2 = __shfl_down_sync(0xffffffffu, pd, 2);
    if (lane < F2 && (lane % 3) == 0) {
        g_al2s[node * H2 + lane / 3] = ps + ps1 + ps2;
        g_al2d[node * H2 + lane / 3] = pd + pd1 + pd2;
    }
}

// ---------------- K5: layer-2 edge pass (8 lanes per edge) ------------------
__global__ void edge2_kernel(const void* __restrict__ ei) {
    int id = blockIdx.x * blockDim.x + threadIdx.x;
    int e = id >> 3;
    int l = id & 7;
    if (e >= N_EDGES) return;
    int is64 = g_is64;
    int src = edge_idx(ei, e, is64);
    int dst = edge_idx(ei, N_EDGES + e, is64);

    float al = g_al2s[src * H2 + l] + g_al2d[dst * H2 + l];
    float ex = __expf(leaky(al));
    atomicAdd(&g_s2[dst * H2 + l], ex);

    const float* xs = &g_xw2[(size_t)src * F2];
    float*       od = &g_out2[(size_t)dst * F2];
    int lane = threadIdx.x & 31;
    int gb = lane & 24;
#pragma unroll
    for (int j = 0; j < 3; j++) {
        int idx = j * 8 + l;          // 0..23, covers h = idx/3
        int h = idx / 3;
        float exh = __shfl_sync(0xffffffffu, ex, gb + h, 32);
        atomicAdd(&od[idx], exh * xs[idx]);
    }
}

// ---------------- K6: finalize layer 2, head-mean, softmax ------------------
__global__ void fin2_kernel(const float* __restrict__ b2,
                            float* __restrict__ out) {
    int n = blockIdx.x * blockDim.x + threadIdx.x;
    if (n >= N_NODES) return;

    float logit[3] = {0.f, 0.f, 0.f};
#pragma unroll
    for (int h = 0; h < H2; h++) {
        float al  = g_al2s[n * H2 + h] + g_al2d[n * H2 + h];
        float exs = __expf(leaky(al));
        float s   = g_s2[n * H2 + h] + exs;
        float inv = 1.f / (s + 1e-16f);
#pragma unroll
        for (int c = 0; c < 3; c++) {
            int idx = n * F2 + h * 3 + c;
            logit[c] += (g_out2[idx] + exs * g_xw2[idx]) * inv;
        }
    }
    float l0 = logit[0] * 0.125f + b2[0];
    float l1 = logit[1] * 0.125f + b2[1];
    float l2 = logit[2] * 0.125f + b2[2];
    float m = fmaxf(l0, fmaxf(l1, l2));
    float e0 = __expf(l0 - m), e1 = __expf(l1 - m), e2 = __expf(l2 - m);
    float inv = 1.f / (e0 + e1 + e2);
    out[n * 3 + 0] = e0 * inv;
    out[n * 3 + 1] = e1 * inv;
    out[n * 3 + 2] = e2 * inv;
}

// ---------------- launch ----------------------------------------------------
extern "C" void kernel_launch(void* const* d_in, const int* in_sizes, int n_in,
                              void* d_out, int out_size) {
    const float* x   = (const float*)d_in[0];
    const float* W1  = (const float*)d_in[1];
    const float* a1s = (const float*)d_in[2];
    const float* a1d = (const float*)d_in[3];
    const float* b1  = (const float*)d_in[4];
    const float* W2  = (const float*)d_in[5];
    const float* a2s = (const float*)d_in[6];
    const float* a2d = (const float*)d_in[7];
    const float* b2  = (const float*)d_in[8];
    const void*  ei  = (const void*)d_in[9];
    float* out = (float*)d_out;

    (void)in_sizes; (void)n_in; (void)out_size;

    detect_kernel<<<1, 32>>>((const unsigned int*)ei);
    zero_kernel<<<(N_NODES * F1 / 4 + 255) / 256, 256>>>();
    gemm1_kernel<<<(N_NODES + 63) / 64, 256>>>(x, W1, a1s, a1d);
    edge1_kernel<<<(N_EDGES * 8) / 256, 256>>>(ei);
    fin1_kernel<<<(N_NODES * H1) / 256, 256>>>(b1);
    gemm2_kernel<<<N_NODES / 8, 256>>>(W2, a2s, a2d);
    edge2_kernel<<<(N_EDGES * 8) / 256, 256>>>(ei);
    fin2_kernel<<<(N_NODES + 255) / 256, 256>>>(b2, out);
}

// round 4
// speedup vs baseline: 1.5075x; 1.5075x over previous
#include <cuda_runtime.h>
#include <cuda_bf16.h>
#include <cstdint>

#define N_NODES 100000
#define N_EDGES 1600000
#define IN_CH   500
#define F1      64
#define H1      8
#define H2      8
#define F2      24
#define NEG_SLOPE 0.2f

#define KPAD    512
#define KC      32            // K per chunk
#define NCHUNK  16
#define ASTR    40            // smem row stride in bf16 elems (80 B)

// ---------------- scratch -----------------------------------------------
__device__ float g_xw1 [N_NODES * F1];
__device__ float g_out1[N_NODES * F1];
__device__ float g_h1  [N_NODES * F1];
__device__ float g_al1s[N_NODES * H1];
__device__ float g_al1d[N_NODES * H1];
__device__ float g_s1  [N_NODES * H1];
__device__ float g_xw2 [N_NODES * F2];
__device__ float g_out2[N_NODES * F2];
__device__ float g_al2s[N_NODES * H2];
__device__ float g_al2d[N_NODES * H2];
__device__ float g_s2  [N_NODES * H2];
__device__ int   g_is64;
__device__ __nv_bfloat16 g_wt_hi[F1 * KPAD];   // W1^T split, [n][k]
__device__ __nv_bfloat16 g_wt_lo[F1 * KPAD];

// ---------------- helpers ------------------------------------------------
__device__ __forceinline__ uint32_t smem_u32(const void* p) {
    uint32_t a;
    asm("{ .reg .u64 t; cvta.to.shared.u64 t, %1; cvt.u32.u64 %0, t; }"
        : "=r"(a) : "l"(p));
    return a;
}
__device__ __forceinline__ float leaky(float v) {
    return v > 0.f ? v : NEG_SLOPE * v;
}
__device__ __forceinline__ int edge_idx(const void* ei, int pos, int is64) {
    if (is64) return (int)((const long long*)ei)[pos];
    return ((const int*)ei)[pos];
}
__device__ __forceinline__ void red4(float* p, float a, float b, float c, float d) {
    asm volatile("red.global.add.v4.f32 [%0], {%1,%2,%3,%4};"
                 :: "l"(p), "f"(a), "f"(b), "f"(c), "f"(d) : "memory");
}

#define LDMX4(r, addr) \
    asm volatile("ldmatrix.sync.aligned.m8n8.x4.shared.b16 {%0,%1,%2,%3}, [%4];" \
        : "=r"((r)[0]), "=r"((r)[1]), "=r"((r)[2]), "=r"((r)[3]) : "r"(addr))

#define MMA_BF16(d, a, b0v, b1v) \
    asm volatile("mma.sync.aligned.m16n8k16.row.col.f32.bf16.bf16.f32 " \
        "{%0,%1,%2,%3}, {%4,%5,%6,%7}, {%8,%9}, {%0,%1,%2,%3};" \
        : "+f"((d)[0]), "+f"((d)[1]), "+f"((d)[2]), "+f"((d)[3]) \
        : "r"((a)[0]), "r"((a)[1]), "r"((a)[2]), "r"((a)[3]), \
          "r"(b0v), "r"(b1v))

// ---------------- detect edge_index dtype --------------------------------
__global__ void detect_kernel(const unsigned int* __restrict__ ei) {
    if (threadIdx.x == 0 && blockIdx.x == 0) {
        int all0 = 1;
        for (int i = 0; i < 64; i++)
            if (ei[2 * i + 1] != 0u) { all0 = 0; break; }
        g_is64 = all0;
    }
}

// ---------------- zero accumulators --------------------------------------
__global__ void zero_kernel() {
    int i = blockIdx.x * blockDim.x + threadIdx.x;
    float4 z = make_float4(0.f, 0.f, 0.f, 0.f);
    if (i < (N_NODES * F1) / 4) ((float4*)g_out1)[i] = z;
    if (i < (N_NODES * F2) / 4) ((float4*)g_out2)[i] = z;
    if (i < (N_NODES * H1) / 4) {
        ((float4*)g_s1)[i] = z;
        ((float4*)g_s2)[i] = z;
    }
}

// ---------------- W1 transpose + bf16 split ------------------------------
__global__ void prep_w_kernel(const float* __restrict__ W) {
    int i = blockIdx.x * blockDim.x + threadIdx.x;
    if (i >= F1 * KPAD) return;
    int n = i >> 9, k = i & 511;
    float v = (k < IN_CH) ? W[k * F1 + n] : 0.f;
    __nv_bfloat16 h = __float2bfloat16(v);
    float lo = v - __bfloat162float(h);
    g_wt_hi[i] = h;
    g_wt_lo[i] = __float2bfloat16(lo);
}

// ---------------- gemm1: mma.sync bf16 3x-split, fused logits ------------
__global__ void __launch_bounds__(256) gemm1_mma(
        const float* __restrict__ x,
        const float* __restrict__ a1s,
        const float* __restrict__ a1d) {
    __shared__ __align__(16) __nv_bfloat16 sAhi[128 * ASTR];
    __shared__ __align__(16) __nv_bfloat16 sAlo[128 * ASTR];
    __shared__ __align__(16) __nv_bfloat16 sBhi[64 * ASTR];
    __shared__ __align__(16) __nv_bfloat16 sBlo[64 * ASTR];

    const int tid = threadIdx.x;
    const int lane = tid & 31, w = tid >> 5;
    const int wm = w >> 1, wn = w & 1;   // warp tile: rows wm*32, cols wn*32
    const int m0 = blockIdx.x * 128;

    const uint32_t aHi = smem_u32(sAhi), aLo = smem_u32(sAlo);
    const uint32_t bHi = smem_u32(sBhi), bLo = smem_u32(sBlo);

    float acc[2][4][4];
#pragma unroll
    for (int i = 0; i < 2; i++)
#pragma unroll
        for (int j = 0; j < 4; j++)
#pragma unroll
            for (int q = 0; q < 4; q++) acc[i][j][q] = 0.f;

    for (int ch = 0; ch < NCHUNK; ch++) {
        const int k0 = ch * KC;

        // -- fetch A chunk to regs --
        float4 av[4];
        int arow[4], ak[4];
#pragma unroll
        for (int p = 0; p < 4; p++) {
            int idx = p * 256 + tid;          // 0..1023
            arow[p] = idx >> 3;
            ak[p] = (idx & 7) * 4;
            int rg = m0 + arow[p], kg = k0 + ak[p];
            av[p] = make_float4(0.f, 0.f, 0.f, 0.f);
            if (rg < N_NODES && kg < IN_CH)
                av[p] = *(const float4*)&x[(size_t)rg * IN_CH + kg];
        }
        // -- fetch B chunk to regs --
        uint2 bh[2], bl[2];
        int bn[2], bk[2];
#pragma unroll
        for (int p = 0; p < 2; p++) {
            int idx = p * 256 + tid;          // 0..511
            bn[p] = idx >> 3;
            bk[p] = (idx & 7) * 4;
            bh[p] = *(const uint2*)&g_wt_hi[bn[p] * KPAD + k0 + bk[p]];
            bl[p] = *(const uint2*)&g_wt_lo[bn[p] * KPAD + k0 + bk[p]];
        }

        __syncthreads();   // prior chunk's MMAs done -> smem reusable

#pragma unroll
        for (int p = 0; p < 4; p++) {
            float4 v = av[p];
            __nv_bfloat16 h0 = __float2bfloat16(v.x), h1 = __float2bfloat16(v.y),
                          h2 = __float2bfloat16(v.z), h3 = __float2bfloat16(v.w);
            __nv_bfloat16 l0 = __float2bfloat16(v.x - __bfloat162float(h0));
            __nv_bfloat16 l1 = __float2bfloat16(v.y - __bfloat162float(h1));
            __nv_bfloat16 l2 = __float2bfloat16(v.z - __bfloat162float(h2));
            __nv_bfloat16 l3 = __float2bfloat16(v.w - __bfloat162float(h3));
            uint32_t hi01 = ((uint32_t)__bfloat16_as_ushort(h1) << 16) | __bfloat16_as_ushort(h0);
            uint32_t hi23 = ((uint32_t)__bfloat16_as_ushort(h3) << 16) | __bfloat16_as_ushort(h2);
            uint32_t lo01 = ((uint32_t)__bfloat16_as_ushort(l1) << 16) | __bfloat16_as_ushort(l0);
            uint32_t lo23 = ((uint32_t)__bfloat16_as_ushort(l3) << 16) | __bfloat16_as_ushort(l2);
            uint32_t off = (uint32_t)(arow[p] * ASTR + ak[p]) * 2;
            asm volatile("st.shared.v2.b32 [%0], {%1,%2};" :: "r"(aHi + off), "r"(hi01), "r"(hi23) : "memory");
            asm volatile("st.shared.v2.b32 [%0], {%1,%2};" :: "r"(aLo + off), "r"(lo01), "r"(lo23) : "memory");
        }
#pragma unroll
        for (int p = 0; p < 2; p++) {
            uint32_t off = (uint32_t)(bn[p] * ASTR + bk[p]) * 2;
            asm volatile("st.shared.v2.b32 [%0], {%1,%2};" :: "r"(bHi + off), "r"(bh[p].x), "r"(bh[p].y) : "memory");
            asm volatile("st.shared.v2.b32 [%0], {%1,%2};" :: "r"(bLo + off), "r"(bl[p].x), "r"(bl[p].y) : "memory");
        }
        __syncthreads();

#pragma unroll
        for (int ks = 0; ks < KC; ks += 16) {
            uint32_t ra_hi[2][4], ra_lo[2][4], rb_hi[2][4], rb_lo[2][4];
#pragma unroll
            for (int mt = 0; mt < 2; mt++) {
                uint32_t roff = (uint32_t)((wm * 32 + mt * 16 + (lane & 15)) * (ASTR * 2))
                              + ks * 2 + (lane & 16);
                LDMX4(ra_hi[mt], aHi + roff);
                LDMX4(ra_lo[mt], aLo + roff);
            }
#pragma unroll
            for (int pr = 0; pr < 2; pr++) {
                uint32_t n = wn * 32 + pr * 16 + (lane & 7) + ((lane & 16) >> 1);
                uint32_t roff = n * (ASTR * 2) + ks * 2 + ((lane & 8) << 1);
                LDMX4(rb_hi[pr], bHi + roff);
                LDMX4(rb_lo[pr], bLo + roff);
            }
#pragma unroll
            for (int mt = 0; mt < 2; mt++)
#pragma unroll
                for (int nt = 0; nt < 4; nt++) {
                    int pr = nt >> 1, sb = (nt & 1) * 2;
                    MMA_BF16(acc[mt][nt], ra_hi[mt], rb_hi[pr][sb], rb_hi[pr][sb + 1]);
                    MMA_BF16(acc[mt][nt], ra_lo[mt], rb_hi[pr][sb], rb_hi[pr][sb + 1]);
                    MMA_BF16(acc[mt][nt], ra_hi[mt], rb_lo[pr][sb], rb_lo[pr][sb + 1]);
                }
        }
    }

    // ---- epilogue: store xw1 + fused per-head logits ----
    const int t = lane & 3, g = lane >> 2;
    float as0[4], as1[4], ad0[4], ad1[4];
#pragma unroll
    for (int nt = 0; nt < 4; nt++) {
        int c = wn * 32 + nt * 8 + 2 * t;
        as0[nt] = __ldg(&a1s[c]);  as1[nt] = __ldg(&a1s[c + 1]);
        ad0[nt] = __ldg(&a1d[c]);  ad1[nt] = __ldg(&a1d[c + 1]);
    }
#pragma unroll
    for (int mt = 0; mt < 2; mt++) {
        int r0 = m0 + wm * 32 + mt * 16 + g;
        int r1 = r0 + 8;
#pragma unroll
        for (int nt = 0; nt < 4; nt++) {
            int c = wn * 32 + nt * 8 + 2 * t;
            if (r0 < N_NODES)
                *(float2*)&g_xw1[(size_t)r0 * F1 + c] = make_float2(acc[mt][nt][0], acc[mt][nt][1]);
            if (r1 < N_NODES)
                *(float2*)&g_xw1[(size_t)r1 * F1 + c] = make_float2(acc[mt][nt][2], acc[mt][nt][3]);
        }
#pragma unroll
        for (int rsel = 0; rsel < 2; rsel++) {
            int row = rsel ? r1 : r0;
#pragma unroll
            for (int nt = 0; nt < 4; nt++) {
                float ps = acc[mt][nt][2 * rsel] * as0[nt] + acc[mt][nt][2 * rsel + 1] * as1[nt];
                float pd = acc[mt][nt][2 * rsel] * ad0[nt] + acc[mt][nt][2 * rsel + 1] * ad1[nt];
                ps += __shfl_xor_sync(0xffffffffu, ps, 1);
                ps += __shfl_xor_sync(0xffffffffu, ps, 2);
                pd += __shfl_xor_sync(0xffffffffu, pd, 1);
                pd += __shfl_xor_sync(0xffffffffu, pd, 2);
                if (t == 0 && row < N_NODES) {
                    g_al1s[row * H1 + wn * 4 + nt] = ps;
                    g_al1d[row * H1 + wn * 4 + nt] = pd;
                }
            }
        }
    }
}

// ---------------- layer-1 edge pass: 16 lanes/edge, vector red ------------
__global__ void edge1_kernel(const void* __restrict__ ei) {
    int id = blockIdx.x * blockDim.x + threadIdx.x;   // 16 * N_EDGES
    int e = id >> 4;
    if (e >= N_EDGES) return;
    int q = id & 15;
    int lane = threadIdx.x & 31;
    int base = lane & 16;
    int is64 = g_is64;
    int src = 0, dst = 0;
    if (q == 0) {
        src = edge_idx(ei, e, is64);
        dst = edge_idx(ei, N_EDGES + e, is64);
    }
    src = __shfl_sync(0xffffffffu, src, base, 32);
    dst = __shfl_sync(0xffffffffu, dst, base, 32);

    float ex_own = 0.f;
    if (q < 8) {
        float al = g_al1s[src * H1 + q] + g_al1d[dst * H1 + q];
        ex_own = __expf(leaky(al));
    }
    float ex = __shfl_sync(0xffffffffu, ex_own, base + (q >> 1), 32);

    float4 v = *(const float4*)&g_xw1[(size_t)src * F1 + q * 4];
    red4(&g_out1[(size_t)dst * F1 + q * 4], v.x * ex, v.y * ex, v.z * ex, v.w * ex);

    int g = (q >> 3) * 4;
    float e0 = __shfl_sync(0xffffffffu, ex_own, base + g + 0, 32);
    float e1 = __shfl_sync(0xffffffffu, ex_own, base + g + 1, 32);
    float e2 = __shfl_sync(0xffffffffu, ex_own, base + g + 2, 32);
    float e3 = __shfl_sync(0xffffffffu, ex_own, base + g + 3, 32);
    if ((q & 7) == 0)
        red4(&g_s1[dst * H1 + g], e0, e1, e2, e3);
}

// ---------------- finalize layer 1 ----------------------------------------
__global__ void fin1_kernel(const float* __restrict__ b1) {
    int id = blockIdx.x * blockDim.x + threadIdx.x;
    if (id >= N_NODES * H1) return;
    int n = id >> 3, h = id & 7;

    float al  = g_al1s[id] + g_al1d[id];
    float exs = __expf(leaky(al));
    float s   = g_s1[id] + exs;
    float inv = 1.f / (s + 1e-16f);

    size_t base = (size_t)n * F1 + h * 8;
    float4 o0 = *(const float4*)&g_out1[base];
    float4 o1 = *(const float4*)&g_out1[base + 4];
    float4 x0 = *(const float4*)&g_xw1[base];
    float4 x1 = *(const float4*)&g_xw1[base + 4];
    float4 bb0 = *(const float4*)&b1[h * 8];
    float4 bb1 = *(const float4*)&b1[h * 8 + 4];

    float v[8];
    v[0] = (o0.x + exs * x0.x) * inv + bb0.x;
    v[1] = (o0.y + exs * x0.y) * inv + bb0.y;
    v[2] = (o0.z + exs * x0.z) * inv + bb0.z;
    v[3] = (o0.w + exs * x0.w) * inv + bb0.w;
    v[4] = (o1.x + exs * x1.x) * inv + bb1.x;
    v[5] = (o1.y + exs * x1.y) * inv + bb1.y;
    v[6] = (o1.z + exs * x1.z) * inv + bb1.z;
    v[7] = (o1.w + exs * x1.w) * inv + bb1.w;
#pragma unroll
    for (int i = 0; i < 8; i++)
        v[i] = v[i] > 0.f ? v[i] : expm1f(v[i]);
    *(float4*)&g_h1[base]     = make_float4(v[0], v[1], v[2], v[3]);
    *(float4*)&g_h1[base + 4] = make_float4(v[4], v[5], v[6], v[7]);
}

// ---------------- gemm2 + layer-2 logits ----------------------------------
__global__ void gemm2_kernel(const float* __restrict__ W2,
                             const float* __restrict__ a2s,
                             const float* __restrict__ a2d) {
    __shared__ float w2s[64 * F2];
    __shared__ float hs[8][64];
    int tid = threadIdx.x, lane = tid & 31, w = tid >> 5;
    for (int i = tid; i < 64 * F2; i += 256) w2s[i] = W2[i];
    __syncthreads();

    int node = blockIdx.x * 8 + w;
    if (node >= N_NODES) return;

    hs[w][lane]      = g_h1[(size_t)node * F1 + lane];
    hs[w][lane + 32] = g_h1[(size_t)node * F1 + 32 + lane];
    __syncwarp();

    float acc = 0.f;
    if (lane < F2) {
#pragma unroll 8
        for (int k = 0; k < 64; k++) acc += hs[w][k] * w2s[k * F2 + lane];
        g_xw2[(size_t)node * F2 + lane] = acc;
    }
    float ps = (lane < F2) ? acc * a2s[lane] : 0.f;
    float pd = (lane < F2) ? acc * a2d[lane] : 0.f;
    float ps1 = __shfl_down_sync(0xffffffffu, ps, 1);
    float ps2 = __shfl_down_sync(0xffffffffu, ps, 2);
    float pd1 = __shfl_down_sync(0xffffffffu, pd, 1);
    float pd2 = __shfl_down_sync(0xffffffffu, pd, 2);
    if (lane < F2 && (lane % 3) == 0) {
        g_al2s[node * H2 + lane / 3] = ps + ps1 + ps2;
        g_al2d[node * H2 + lane / 3] = pd + pd1 + pd2;
    }
}

// ---------------- layer-2 edge pass: 8 lanes/edge, vector red --------------
__global__ void edge2_kernel(const void* __restrict__ ei) {
    int id = blockIdx.x * blockDim.x + threadIdx.x;   // 8 * N_EDGES
    int e = id >> 3;
    if (e >= N_EDGES) return;
    int q = id & 7;
    int lane = threadIdx.x & 31;
    int base = lane & 24;
    int is64 = g_is64;
    int src = 0, dst = 0;
    if (q == 0) {
        src = edge_idx(ei, e, is64);
        dst = edge_idx(ei, N_EDGES + e, is64);
    }
    src = __shfl_sync(0xffffffffu, src, base, 32);
    dst = __shfl_sync(0xffffffffu, dst, base, 32);

    float al = g_al2s[src * H2 + q] + g_al2d[dst * H2 + q];
    float ex_own = __expf(leaky(al));

    int f = q * 4;
    float e0 = __shfl_sync(0xffffffffu, ex_own, base + min((f + 0) / 3, 7), 32);
    float e1 = __shfl_sync(0xffffffffu, ex_own, base + min((f + 1) / 3, 7), 32);
    float e2 = __shfl_sync(0xffffffffu, ex_own, base + min((f + 2) / 3, 7), 32);
    float e3 = __shfl_sync(0xffffffffu, ex_own, base + min((f + 3) / 3, 7), 32);
    if (q < 6) {
        float4 v = *(const float4*)&g_xw2[(size_t)src * F2 + f];
        red4(&g_out2[(size_t)dst * F2 + f], v.x * e0, v.y * e1, v.z * e2, v.w * e3);
    }

    int g = (q >> 2) * 4;
    float s0 = __shfl_sync(0xffffffffu, ex_own, base + g + 0, 32);
    float s1 = __shfl_sync(0xffffffffu, ex_own, base + g + 1, 32);
    float s2 = __shfl_sync(0xffffffffu, ex_own, base + g + 2, 32);
    float s3 = __shfl_sync(0xffffffffu, ex_own, base + g + 3, 32);
    if ((q & 3) == 0)
        red4(&g_s2[dst * H2 + g], s0, s1, s2, s3);
}

// ---------------- finalize layer 2, head-mean, softmax ---------------------
__global__ void fin2_kernel(const float* __restrict__ b2,
                            float* __restrict__ out) {
    int n = blockIdx.x * blockDim.x + threadIdx.x;
    if (n >= N_NODES) return;

    float logit[3] = {0.f, 0.f, 0.f};
#pragma unroll
    for (int h = 0; h < H2; h++) {
        float al  = g_al2s[n * H2 + h] + g_al2d[n * H2 + h];
        float exs = __expf(leaky(al));
        float s   = g_s2[n * H2 + h] + exs;
        float inv = 1.f / (s + 1e-16f);
#pragma unroll
        for (int c = 0; c < 3; c++) {
            int idx = n * F2 + h * 3 + c;
            logit[c] += (g_out2[idx] + exs * g_xw2[idx]) * inv;
        }
    }
    float l0 = logit[0] * 0.125f + b2[0];
    float l1 = logit[1] * 0.125f + b2[1];
    float l2 = logit[2] * 0.125f + b2[2];
    float m = fmaxf(l0, fmaxf(l1, l2));
    float e0 = __expf(l0 - m), e1 = __expf(l1 - m), e2 = __expf(l2 - m);
    float inv = 1.f / (e0 + e1 + e2);
    out[n * 3 + 0] = e0 * inv;
    out[n * 3 + 1] = e1 * inv;
    out[n * 3 + 2] = e2 * inv;
}

// ---------------- launch ----------------------------------------------------
extern "C" void kernel_launch(void* const* d_in, const int* in_sizes, int n_in,
                              void* d_out, int out_size) {
    const float* x   = (const float*)d_in[0];
    const float* W1  = (const float*)d_in[1];
    const float* a1s = (const float*)d_in[2];
    const float* a1d = (const float*)d_in[3];
    const float* b1  = (const float*)d_in[4];
    const float* W2  = (const float*)d_in[5];
    const float* a2s = (const float*)d_in[6];
    const float* a2d = (const float*)d_in[7];
    const float* b2  = (const float*)d_in[8];
    const void*  ei  = (const void*)d_in[9];
    float* out = (float*)d_out;

    (void)in_sizes; (void)n_in; (void)out_size;

    detect_kernel<<<1, 32>>>((const unsigned int*)ei);
    zero_kernel<<<(N_NODES * F1 / 4 + 255) / 256, 256>>>();
    prep_w_kernel<<<(F1 * KPAD + 255) / 256, 256>>>(W1);
    gemm1_mma<<<(N_NODES + 127) / 128, 256>>>(x, a1s, a1d);
    edge1_kernel<<<(N_EDGES * 16) / 256, 256>>>(ei);
    fin1_kernel<<<(N_NODES * H1) / 256, 256>>>(b1);
    gemm2_kernel<<<N_NODES / 8, 256>>>(W2, a2s, a2d);
    edge2_kernel<<<(N_EDGES * 8) / 256, 256>>>(ei);
    fin2_kernel<<<(N_NODES + 255) / 256, 256>>>(b2, out);
}

// round 5
// speedup vs baseline: 1.6723x; 1.1093x over previous
#include <cuda_runtime.h>
#include <cuda_bf16.h>
#include <cstdint>

#define N_NODES 100000
#define N_EDGES 1600000
#define IN_CH   500
#define F1      64
#define H1      8
#define H2      8
#define F2      24
#define NEG_SLOPE 0.2f

#define KPAD    512
#define KC      32            // K per chunk
#define NCHUNK  16
#define ASTR    40            // smem row stride in bf16 elems (80 B)

// dynamic smem layout for gemm1 (bytes)
#define SZ_A    (128 * ASTR * 2)        // 10240 per buffer
#define SZ_B    (64 * ASTR * 2)         // 5120 per buffer
#define OFF_AHI 0
#define OFF_ALO (2 * SZ_A)              // 20480
#define OFF_BHI (4 * SZ_A)              // 40960
#define OFF_BLO (4 * SZ_A + 2 * SZ_B)   // 51200
#define SM_TOTAL (4 * SZ_A + 4 * SZ_B)  // 61440

// ---------------- scratch -----------------------------------------------
__device__ float g_xw1 [N_NODES * F1];
__device__ float g_out1[N_NODES * F1];
__device__ float g_h1  [N_NODES * F1];
__device__ float g_al1s[N_NODES * H1];
__device__ float g_al1d[N_NODES * H1];
__device__ float g_s1  [N_NODES * H1];
__device__ float g_xw2 [N_NODES * F2];
__device__ float g_out2[N_NODES * F2];
__device__ float g_al2s[N_NODES * H2];
__device__ float g_al2d[N_NODES * H2];
__device__ float g_s2  [N_NODES * H2];
__device__ int   g_is64;
__device__ __nv_bfloat16 g_wt_hi[F1 * KPAD];   // W1^T split, [n][k]
__device__ __nv_bfloat16 g_wt_lo[F1 * KPAD];

// ---------------- helpers ------------------------------------------------
__device__ __forceinline__ uint32_t smem_u32(const void* p) {
    uint32_t a;
    asm("{ .reg .u64 t; cvta.to.shared.u64 t, %1; cvt.u32.u64 %0, t; }"
        : "=r"(a) : "l"(p));
    return a;
}
__device__ __forceinline__ float leaky(float v) {
    return v > 0.f ? v : NEG_SLOPE * v;
}
__device__ __forceinline__ int edge_idx(const void* ei, int pos, int is64) {
    if (is64) return (int)((const long long*)ei)[pos];
    return ((const int*)ei)[pos];
}
__device__ __forceinline__ void red4(float* p, float a, float b, float c, float d) {
    asm volatile("red.global.add.v4.f32 [%0], {%1,%2,%3,%4};"
                 :: "l"(p), "f"(a), "f"(b), "f"(c), "f"(d) : "memory");
}
__device__ __forceinline__ void cp16(uint32_t dst, const void* src) {
    asm volatile("cp.async.ca.shared.global [%0], [%1], 16;"
                 :: "r"(dst), "l"(src) : "memory");
}

#define LDMX4(r, addr) \
    asm volatile("ldmatrix.sync.aligned.m8n8.x4.shared.b16 {%0,%1,%2,%3}, [%4];" \
        : "=r"((r)[0]), "=r"((r)[1]), "=r"((r)[2]), "=r"((r)[3]) : "r"(addr))

#define MMA_BF16(d, a, b0v, b1v) \
    asm volatile("mma.sync.aligned.m16n8k16.row.col.f32.bf16.bf16.f32 " \
        "{%0,%1,%2,%3}, {%4,%5,%6,%7}, {%8,%9}, {%0,%1,%2,%3};" \
        : "+f"((d)[0]), "+f"((d)[1]), "+f"((d)[2]), "+f"((d)[3]) \
        : "r"((a)[0]), "r"((a)[1]), "r"((a)[2]), "r"((a)[3]), \
          "r"(b0v), "r"(b1v))

// ---------------- detect edge_index dtype --------------------------------
__global__ void detect_kernel(const unsigned int* __restrict__ ei) {
    if (threadIdx.x == 0 && blockIdx.x == 0) {
        int all0 = 1;
        for (int i = 0; i < 64; i++)
            if (ei[2 * i + 1] != 0u) { all0 = 0; break; }
        g_is64 = all0;
    }
}

// ---------------- zero accumulators --------------------------------------
__global__ void zero_kernel() {
    int i = blockIdx.x * blockDim.x + threadIdx.x;
    float4 z = make_float4(0.f, 0.f, 0.f, 0.f);
    if (i < (N_NODES * F1) / 4) ((float4*)g_out1)[i] = z;
    if (i < (N_NODES * F2) / 4) ((float4*)g_out2)[i] = z;
    if (i < (N_NODES * H1) / 4) {
        ((float4*)g_s1)[i] = z;
        ((float4*)g_s2)[i] = z;
    }
}

// ---------------- W1 transpose + bf16 split ------------------------------
__global__ void prep_w_kernel(const float* __restrict__ W) {
    int i = blockIdx.x * blockDim.x + threadIdx.x;
    if (i >= F1 * KPAD) return;
    int n = i >> 9, k = i & 511;
    float v = (k < IN_CH) ? W[k * F1 + n] : 0.f;
    __nv_bfloat16 h = __float2bfloat16(v);
    float lo = v - __bfloat162float(h);
    g_wt_hi[i] = h;
    g_wt_lo[i] = __float2bfloat16(lo);
}

// ---------------- gemm1: pipelined mma.sync bf16 3x-split ----------------
__global__ void __launch_bounds__(256) gemm1_mma(
        const float* __restrict__ x,
        const float* __restrict__ a1s,
        const float* __restrict__ a1d) {
    extern __shared__ char smem[];
    const uint32_t sb = smem_u32(smem);

    const int tid = threadIdx.x;
    const int lane = tid & 31, w = tid >> 5;
    const int wm = w >> 1, wn = w & 1;
    const int m0 = blockIdx.x * 128;

    float acc[2][4][4];
#pragma unroll
    for (int i = 0; i < 2; i++)
#pragma unroll
        for (int j = 0; j < 4; j++)
#pragma unroll
            for (int q = 0; q < 4; q++) acc[i][j][q] = 0.f;

    // per-thread A tile coordinates (fixed across chunks)
    int arow[4], ak[4];
#pragma unroll
    for (int p = 0; p < 4; p++) {
        int idx = p * 256 + tid;
        arow[p] = idx >> 3;
        ak[p] = (idx & 7) * 4;
    }
    const int brow = tid >> 2;          // B cp.async coords
    const int bke  = (tid & 3) * 8;     // element offset within chunk

    float4 av[4];

    // -- issue loads for chunk 0 into buffer 0 --
    {
        const int k0 = 0;
        cp16(sb + OFF_BHI + (uint32_t)(brow * ASTR + bke) * 2,
             &g_wt_hi[brow * KPAD + k0 + bke]);
        cp16(sb + OFF_BLO + (uint32_t)(brow * ASTR + bke) * 2,
             &g_wt_lo[brow * KPAD + k0 + bke]);
        asm volatile("cp.async.commit_group;" ::: "memory");
#pragma unroll
        for (int p = 0; p < 4; p++) {
            int rg = m0 + arow[p], kg = k0 + ak[p];
            av[p] = make_float4(0.f, 0.f, 0.f, 0.f);
            if (rg < N_NODES && kg < IN_CH)
                av[p] = *(const float4*)&x[(size_t)rg * IN_CH + kg];
        }
        // convert + store A into buffer 0
#pragma unroll
        for (int p = 0; p < 4; p++) {
            float4 v = av[p];
            __nv_bfloat16 h0 = __float2bfloat16(v.x), h1 = __float2bfloat16(v.y),
                          h2 = __float2bfloat16(v.z), h3 = __float2bfloat16(v.w);
            __nv_bfloat16 l0 = __float2bfloat16(v.x - __bfloat162float(h0));
            __nv_bfloat16 l1 = __float2bfloat16(v.y - __bfloat162float(h1));
            __nv_bfloat16 l2 = __float2bfloat16(v.z - __bfloat162float(h2));
            __nv_bfloat16 l3 = __float2bfloat16(v.w - __bfloat162float(h3));
            uint32_t hi01 = ((uint32_t)__bfloat16_as_ushort(h1) << 16) | __bfloat16_as_ushort(h0);
            uint32_t hi23 = ((uint32_t)__bfloat16_as_ushort(h3) << 16) | __bfloat16_as_ushort(h2);
            uint32_t lo01 = ((uint32_t)__bfloat16_as_ushort(l1) << 16) | __bfloat16_as_ushort(l0);
            uint32_t lo23 = ((uint32_t)__bfloat16_as_ushort(l3) << 16) | __bfloat16_as_ushort(l2);
            uint32_t off = (uint32_t)(arow[p] * ASTR + ak[p]) * 2;
            asm volatile("st.shared.v2.b32 [%0], {%1,%2};" :: "r"(sb + OFF_AHI + off), "r"(hi01), "r"(hi23) : "memory");
            asm volatile("st.shared.v2.b32 [%0], {%1,%2};" :: "r"(sb + OFF_ALO + off), "r"(lo01), "r"(lo23) : "memory");
        }
        asm volatile("cp.async.wait_group 0;" ::: "memory");
        __syncthreads();
    }

    for (int ch = 0; ch < NCHUNK; ch++) {
        const int pb = ch & 1, nb = pb ^ 1;
        const bool more = (ch + 1) < NCHUNK;

        // -- issue loads for chunk ch+1 into buffer nb (overlap with MMA) --
        if (more) {
            const int k0 = (ch + 1) * KC;
            cp16(sb + OFF_BHI + nb * SZ_B + (uint32_t)(brow * ASTR + bke) * 2,
                 &g_wt_hi[brow * KPAD + k0 + bke]);
            cp16(sb + OFF_BLO + nb * SZ_B + (uint32_t)(brow * ASTR + bke) * 2,
                 &g_wt_lo[brow * KPAD + k0 + bke]);
            asm volatile("cp.async.commit_group;" ::: "memory");
#pragma unroll
            for (int p = 0; p < 4; p++) {
                int rg = m0 + arow[p], kg = k0 + ak[p];
                av[p] = make_float4(0.f, 0.f, 0.f, 0.f);
                if (rg < N_NODES && kg < IN_CH)
                    av[p] = *(const float4*)&x[(size_t)rg * IN_CH + kg];
            }
        }

        // -- MMA on buffer pb --
        const uint32_t aHi = sb + OFF_AHI + pb * SZ_A;
        const uint32_t aLo = sb + OFF_ALO + pb * SZ_A;
        const uint32_t bHi = sb + OFF_BHI + pb * SZ_B;
        const uint32_t bLo = sb + OFF_BLO + pb * SZ_B;
#pragma unroll
        for (int ks = 0; ks < KC; ks += 16) {
            uint32_t ra_hi[2][4], ra_lo[2][4], rb_hi[2][4], rb_lo[2][4];
#pragma unroll
            for (int mt = 0; mt < 2; mt++) {
                uint32_t roff = (uint32_t)((wm * 32 + mt * 16 + (lane & 15)) * (ASTR * 2))
                              + ks * 2 + (lane & 16);
                LDMX4(ra_hi[mt], aHi + roff);
                LDMX4(ra_lo[mt], aLo + roff);
            }
#pragma unroll
            for (int pr = 0; pr < 2; pr++) {
                uint32_t n = wn * 32 + pr * 16 + (lane & 7) + ((lane & 16) >> 1);
                uint32_t roff = n * (ASTR * 2) + ks * 2 + ((lane & 8) << 1);
                LDMX4(rb_hi[pr], bHi + roff);
                LDMX4(rb_lo[pr], bLo + roff);
            }
#pragma unroll
            for (int mt = 0; mt < 2; mt++)
#pragma unroll
                for (int nt = 0; nt < 4; nt++) {
                    int pr = nt >> 1, sbi = (nt & 1) * 2;
                    MMA_BF16(acc[mt][nt], ra_hi[mt], rb_hi[pr][sbi], rb_hi[pr][sbi + 1]);
                    MMA_BF16(acc[mt][nt], ra_lo[mt], rb_hi[pr][sbi], rb_hi[pr][sbi + 1]);
                    MMA_BF16(acc[mt][nt], ra_hi[mt], rb_lo[pr][sbi], rb_lo[pr][sbi + 1]);
                }
        }

        // -- convert + store A regs into buffer nb, finish B, sync --
        if (more) {
#pragma unroll
            for (int p = 0; p < 4; p++) {
                float4 v = av[p];
                __nv_bfloat16 h0 = __float2bfloat16(v.x), h1 = __float2bfloat16(v.y),
                              h2 = __float2bfloat16(v.z), h3 = __float2bfloat16(v.w);
                __nv_bfloat16 l0 = __float2bfloat16(v.x - __bfloat162float(h0));
                __nv_bfloat16 l1 = __float2bfloat16(v.y - __bfloat162float(h1));
                __nv_bfloat16 l2 = __float2bfloat16(v.z - __bfloat162float(h2));
                __nv_bfloat16 l3 = __float2bfloat16(v.w - __bfloat162float(h3));
                uint32_t hi01 = ((uint32_t)__bfloat16_as_ushort(h1) << 16) | __bfloat16_as_ushort(h0);
                uint32_t hi23 = ((uint32_t)__bfloat16_as_ushort(h3) << 16) | __bfloat16_as_ushort(h2);
                uint32_t lo01 = ((uint32_t)__bfloat16_as_ushort(l1) << 16) | __bfloat16_as_ushort(l0);
                uint32_t lo23 = ((uint32_t)__bfloat16_as_ushort(l3) << 16) | __bfloat16_as_ushort(l2);
                uint32_t off = nb * SZ_A + (uint32_t)(arow[p] * ASTR + ak[p]) * 2;
                asm volatile("st.shared.v2.b32 [%0], {%1,%2};" :: "r"(sb + OFF_AHI + off), "r"(hi01), "r"(hi23) : "memory");
                asm volatile("st.shared.v2.b32 [%0], {%1,%2};" :: "r"(sb + OFF_ALO + off), "r"(lo01), "r"(lo23) : "memory");
            }
            asm volatile("cp.async.wait_group 0;" ::: "memory");
            __syncthreads();
        }
    }

    // ---- epilogue: store xw1 + fused per-head logits ----
    const int t = lane & 3, g = lane >> 2;
    float as0[4], as1[4], ad0[4], ad1[4];
#pragma unroll
    for (int nt = 0; nt < 4; nt++) {
        int c = wn * 32 + nt * 8 + 2 * t;
        as0[nt] = __ldg(&a1s[c]);  as1[nt] = __ldg(&a1s[c + 1]);
        ad0[nt] = __ldg(&a1d[c]);  ad1[nt] = __ldg(&a1d[c + 1]);
    }
#pragma unroll
    for (int mt = 0; mt < 2; mt++) {
        int r0 = m0 + wm * 32 + mt * 16 + g;
        int r1 = r0 + 8;
#pragma unroll
        for (int nt = 0; nt < 4; nt++) {
            int c = wn * 32 + nt * 8 + 2 * t;
            if (r0 < N_NODES)
                *(float2*)&g_xw1[(size_t)r0 * F1 + c] = make_float2(acc[mt][nt][0], acc[mt][nt][1]);
            if (r1 < N_NODES)
                *(float2*)&g_xw1[(size_t)r1 * F1 + c] = make_float2(acc[mt][nt][2], acc[mt][nt][3]);
        }
#pragma unroll
        for (int rsel = 0; rsel < 2; rsel++) {
            int row = rsel ? r1 : r0;
#pragma unroll
            for (int nt = 0; nt < 4; nt++) {
                float ps = acc[mt][nt][2 * rsel] * as0[nt] + acc[mt][nt][2 * rsel + 1] * as1[nt];
                float pd = acc[mt][nt][2 * rsel] * ad0[nt] + acc[mt][nt][2 * rsel + 1] * ad1[nt];
                ps += __shfl_xor_sync(0xffffffffu, ps, 1);
                ps += __shfl_xor_sync(0xffffffffu, ps, 2);
                pd += __shfl_xor_sync(0xffffffffu, pd, 1);
                pd += __shfl_xor_sync(0xffffffffu, pd, 2);
                if (t == 0 && row < N_NODES) {
                    g_al1s[row * H1 + wn * 4 + nt] = ps;
                    g_al1d[row * H1 + wn * 4 + nt] = pd;
                }
            }
        }
    }
}

// ---------------- layer-1 edge pass: 16 lanes/edge, vector red ------------
__global__ void edge1_kernel(const void* __restrict__ ei) {
    int id = blockIdx.x * blockDim.x + threadIdx.x;   // 16 * N_EDGES
    int e = id >> 4;
    if (e >= N_EDGES) return;
    int q = id & 15;
    int lane = threadIdx.x & 31;
    int base = lane & 16;
    int is64 = g_is64;
    int src = 0, dst = 0;
    if (q == 0) {
        src = edge_idx(ei, e, is64);
        dst = edge_idx(ei, N_EDGES + e, is64);
    }
    src = __shfl_sync(0xffffffffu, src, base, 32);
    dst = __shfl_sync(0xffffffffu, dst, base, 32);

    float ex_own = 0.f;
    if (q < 8) {
        float al = g_al1s[src * H1 + q] + g_al1d[dst * H1 + q];
        ex_own = __expf(leaky(al));
    }
    float ex = __shfl_sync(0xffffffffu, ex_own, base + (q >> 1), 32);

    float4 v = *(const float4*)&g_xw1[(size_t)src * F1 + q * 4];
    red4(&g_out1[(size_t)dst * F1 + q * 4], v.x * ex, v.y * ex, v.z * ex, v.w * ex);

    int g = (q >> 3) * 4;
    float e0 = __shfl_sync(0xffffffffu, ex_own, base + g + 0, 32);
    float e1 = __shfl_sync(0xffffffffu, ex_own, base + g + 1, 32);
    float e2 = __shfl_sync(0xffffffffu, ex_own, base + g + 2, 32);
    float e3 = __shfl_sync(0xffffffffu, ex_own, base + g + 3, 32);
    if ((q & 7) == 0)
        red4(&g_s1[dst * H1 + g], e0, e1, e2, e3);
}

// ---------------- finalize layer 1 ----------------------------------------
__global__ void fin1_kernel(const float* __restrict__ b1) {
    int id = blockIdx.x * blockDim.x + threadIdx.x;
    if (id >= N_NODES * H1) return;
    int n = id >> 3, h = id & 7;

    float al  = g_al1s[id] + g_al1d[id];
    float exs = __expf(leaky(al));
    float s   = g_s1[id] + exs;
    float inv = 1.f / (s + 1e-16f);

    size_t base = (size_t)n * F1 + h * 8;
    float4 o0 = *(const float4*)&g_out1[base];
    float4 o1 = *(const float4*)&g_out1[base + 4];
    float4 x0 = *(const float4*)&g_xw1[base];
    float4 x1 = *(const float4*)&g_xw1[base + 4];
    float4 bb0 = *(const float4*)&b1[h * 8];
    float4 bb1 = *(const float4*)&b1[h * 8 + 4];

    float v[8];
    v[0] = (o0.x + exs * x0.x) * inv + bb0.x;
    v[1] = (o0.y + exs * x0.y) * inv + bb0.y;
    v[2] = (o0.z + exs * x0.z) * inv + bb0.z;
    v[3] = (o0.w + exs * x0.w) * inv + bb0.w;
    v[4] = (o1.x + exs * x1.x) * inv + bb1.x;
    v[5] = (o1.y + exs * x1.y) * inv + bb1.y;
    v[6] = (o1.z + exs * x1.z) * inv + bb1.z;
    v[7] = (o1.w + exs * x1.w) * inv + bb1.w;
#pragma unroll
    for (int i = 0; i < 8; i++)
        v[i] = v[i] > 0.f ? v[i] : expm1f(v[i]);
    *(float4*)&g_h1[base]     = make_float4(v[0], v[1], v[2], v[3]);
    *(float4*)&g_h1[base + 4] = make_float4(v[4], v[5], v[6], v[7]);
}

// ---------------- gemm2 + layer-2 logits ----------------------------------
__global__ void gemm2_kernel(const float* __restrict__ W2,
                             const float* __restrict__ a2s,
                             const float* __restrict__ a2d) {
    __shared__ float w2s[64 * F2];
    __shared__ float hs[8][64];
    int tid = threadIdx.x, lane = tid & 31, w = tid >> 5;
    for (int i = tid; i < 64 * F2; i += 256) w2s[i] = W2[i];
    __syncthreads();

    int node = blockIdx.x * 8 + w;
    if (node >= N_NODES) return;

    hs[w][lane]      = g_h1[(size_t)node * F1 + lane];
    hs[w][lane + 32] = g_h1[(size_t)node * F1 + 32 + lane];
    __syncwarp();

    float acc = 0.f;
    if (lane < F2) {
#pragma unroll 8
        for (int k = 0; k < 64; k++) acc += hs[w][k] * w2s[k * F2 + lane];
        g_xw2[(size_t)node * F2 + lane] = acc;
    }
    float ps = (lane < F2) ? acc * a2s[lane] : 0.f;
    float pd = (lane < F2) ? acc * a2d[lane] : 0.f;
    float ps1 = __shfl_down_sync(0xffffffffu, ps, 1);
    float ps2 = __shfl_down_sync(0xffffffffu, ps, 2);
    float pd1 = __shfl_down_sync(0xffffffffu, pd, 1);
    float pd2 = __shfl_down_sync(0xffffffffu, pd, 2);
    if (lane < F2 && (lane % 3) == 0) {
        g_al2s[node * H2 + lane / 3] = ps + ps1 + ps2;
        g_al2d[node * H2 + lane / 3] = pd + pd1 + pd2;
    }
}

// ---------------- layer-2 edge pass: 8 lanes/edge, vector red --------------
__global__ void edge2_kernel(const void* __restrict__ ei) {
    int id = blockIdx.x * blockDim.x + threadIdx.x;   // 8 * N_EDGES
    int e = id >> 3;
    if (e >= N_EDGES) return;
    int q = id & 7;
    int lane = threadIdx.x & 31;
    int base = lane & 24;
    int is64 = g_is64;
    int src = 0, dst = 0;
    if (q == 0) {
        src = edge_idx(ei, e, is64);
        dst = edge_idx(ei, N_EDGES + e, is64);
    }
    src = __shfl_sync(0xffffffffu, src, base, 32);
    dst = __shfl_sync(0xffffffffu, dst, base, 32);

    float al = g_al2s[src * H2 + q] + g_al2d[dst * H2 + q];
    float ex_own = __expf(leaky(al));

    int f = q * 4;
    float e0 = __shfl_sync(0xffffffffu, ex_own, base + min((f + 0) / 3, 7), 32);
    float e1 = __shfl_sync(0xffffffffu, ex_own, base + min((f + 1) / 3, 7), 32);
    float e2 = __shfl_sync(0xffffffffu, ex_own, base + min((f + 2) / 3, 7), 32);
    float e3 = __shfl_sync(0xffffffffu, ex_own, base + min((f + 3) / 3, 7), 32);
    if (q < 6) {
        float4 v = *(const float4*)&g_xw2[(size_t)src * F2 + f];
        red4(&g_out2[(size_t)dst * F2 + f], v.x * e0, v.y * e1, v.z * e2, v.w * e3);
    }

    int g = (q >> 2) * 4;
    float s0 = __shfl_sync(0xffffffffu, ex_own, base + g + 0, 32);
    float s1 = __shfl_sync(0xffffffffu, ex_own, base + g + 1, 32);
    float s2 = __shfl_sync(0xffffffffu, ex_own, base + g + 2, 32);
    float s3 = __shfl_sync(0xffffffffu, ex_own, base + g + 3, 32);
    if ((q & 3) == 0)
        red4(&g_s2[dst * H2 + g], s0, s1, s2, s3);
}

// ---------------- finalize layer 2, head-mean, softmax ---------------------
__global__ void fin2_kernel(const float* __restrict__ b2,
                            float* __restrict__ out) {
    int n = blockIdx.x * blockDim.x + threadIdx.x;
    if (n >= N_NODES) return;

    float logit[3] = {0.f, 0.f, 0.f};
#pragma unroll
    for (int h = 0; h < H2; h++) {
        float al  = g_al2s[n * H2 + h] + g_al2d[n * H2 + h];
        float exs = __expf(leaky(al));
        float s   = g_s2[n * H2 + h] + exs;
        float inv = 1.f / (s + 1e-16f);
#pragma unroll
        for (int c = 0; c < 3; c++) {
            int idx = n * F2 + h * 3 + c;
            logit[c] += (g_out2[idx] + exs * g_xw2[idx]) * inv;
        }
    }
    float l0 = logit[0] * 0.125f + b2[0];
    float l1 = logit[1] * 0.125f + b2[1];
    float l2 = logit[2] * 0.125f + b2[2];
    float m = fmaxf(l0, fmaxf(l1, l2));
    float e0 = __expf(l0 - m), e1 = __expf(l1 - m), e2 = __expf(l2 - m);
    float inv = 1.f / (e0 + e1 + e2);
    out[n * 3 + 0] = e0 * inv;
    out[n * 3 + 1] = e1 * inv;
    out[n * 3 + 2] = e2 * inv;
}

// ---------------- launch ----------------------------------------------------
extern "C" void kernel_launch(void* const* d_in, const int* in_sizes, int n_in,
                              void* d_out, int out_size) {
    const float* x   = (const float*)d_in[0];
    const float* W1  = (const float*)d_in[1];
    const float* a1s = (const float*)d_in[2];
    const float* a1d = (const float*)d_in[3];
    const float* b1  = (const float*)d_in[4];
    const float* W2  = (const float*)d_in[5];
    const float* a2s = (const float*)d_in[6];
    const float* a2d = (const float*)d_in[7];
    const float* b2  = (const float*)d_in[8];
    const void*  ei  = (const void*)d_in[9];
    float* out = (float*)d_out;

    (void)in_sizes; (void)n_in; (void)out_size;

    static int attr_done = 0;
    if (!attr_done) {
        cudaFuncSetAttribute(gemm1_mma,
                             cudaFuncAttributeMaxDynamicSharedMemorySize,
                             SM_TOTAL);
        attr_done = 1;
    }

    detect_kernel<<<1, 32>>>((const unsigned int*)ei);
    zero_kernel<<<(N_NODES * F1 / 4 + 255) / 256, 256>>>();
    prep_w_kernel<<<(F1 * KPAD + 255) / 256, 256>>>(W1);
    gemm1_mma<<<(N_NODES + 127) / 128, 256, SM_TOTAL>>>(x, a1s, a1d);
    edge1_kernel<<<(N_EDGES * 16) / 256, 256>>>(ei);
    fin1_kernel<<<(N_NODES * H1) / 256, 256>>>(b1);
    gemm2_kernel<<<N_NODES / 8, 256>>>(W2, a2s, a2d);
    edge2_kernel<<<(N_EDGES * 8) / 256, 256>>>(ei);
    fin2_kernel<<<(N_NODES + 255) / 256, 256>>>(b2, out);
}